// round 4
// baseline (speedup 1.0000x reference)
#include <cuda_runtime.h>
#include <cstdint>

// Batched C[b,n,m] = sum_e A[b,n,e] * B[b,m,e]
// b=8, n=m=2048, e=1024, fp32.
// mma.sync m16n8k8 tf32, 128x256 CTA tile, 512 threads (16 warps, 32x64 warp
// tiles), 4-stage cp.async pipeline, consumer-side cvt.rna.tf32.

#define TM 128
#define TN 256
#define BK 32
#define NSTG 4
#define EDIM 1024
#define NDIM 2048
#define MDIM 2048
#define NB 8
#define NCHUNK (EDIM / BK)
#define A_BYTES (TM * BK * 4)           // 16384
#define B_BYTES (TN * BK * 4)           // 32768
#define STG (A_BYTES + B_BYTES)         // 49152
#define SMEM_BYTES (NSTG * STG)         // 196608

__device__ __forceinline__ uint32_t f2tf32(float f) {
    uint32_t r;
    asm("cvt.rna.tf32.f32 %0, %1;" : "=r"(r) : "f"(f));
    return r;
}
__device__ __forceinline__ float lds32(uint32_t a) {
    float v;
    asm volatile("ld.shared.b32 %0, [%1];" : "=f"(v) : "r"(a));
    return v;
}
__device__ __forceinline__ void cp16(uint32_t dst, const float* src) {
    asm volatile("cp.async.cg.shared.global [%0], [%1], 16;"
                 :: "r"(dst), "l"(src) : "memory");
}

// 512 threads: per thread 2 A-lines + 4 B-lines of 16B per chunk.
// Swizzle: 16B-chunk column XOR (row & 7) -> conflict-free fragment LDS.
__device__ __forceinline__ void issue_chunk(uint32_t sbase, const float* Ab,
                                            const float* Bb, int chunk,
                                            int lr, int lc) {
    uint32_t st = sbase + (chunk & (NSTG - 1)) * STG;
    #pragma unroll
    for (int i = 0; i < 2; i++) {
        int row = lr + 64 * i;
        cp16(st + row * 128 + ((lc ^ (row & 7)) * 16),
             Ab + (size_t)row * EDIM + chunk * BK + lc * 4);
    }
    #pragma unroll
    for (int i = 0; i < 4; i++) {
        int row = lr + 64 * i;
        cp16(st + A_BYTES + row * 128 + ((lc ^ (row & 7)) * 16),
             Bb + (size_t)row * EDIM + chunk * BK + lc * 4);
    }
    asm volatile("cp.async.commit_group;" ::: "memory");
}

__global__ __launch_bounds__(512, 1)
void bmm_tf32_v3(const float* __restrict__ A, const float* __restrict__ B,
                 float* __restrict__ C) {
    extern __shared__ char smem[];
    uint32_t sbase;
    asm("{ .reg .u64 t; cvta.to.shared.u64 t, %1; cvt.u32.u64 %0, t; }"
        : "=r"(sbase) : "l"(smem));

    const int tid  = threadIdx.x;
    const int warp = tid >> 5;
    const int lane = tid & 31;
    const int wm   = warp & 3;        // 4 row blocks of 32
    const int wn   = warp >> 2;       // 4 col blocks of 64
    const int g    = lane >> 2;       // groupID 0..7
    const int t    = lane & 3;        // thread-in-group

    const int b = blockIdx.z, by = blockIdx.y, bx = blockIdx.x;
    const float* Ab = A + ((size_t)b * NDIM + (size_t)by * TM) * EDIM;
    const float* Bb = B + ((size_t)b * MDIM + (size_t)bx * TN) * EDIM;

    const int lr = tid >> 3;          // 0..63
    const int lc = tid & 7;           // 16B chunk 0..7

    float acc[2][8][4];
    #pragma unroll
    for (int i = 0; i < 2; i++)
        #pragma unroll
        for (int j = 0; j < 8; j++)
            #pragma unroll
            for (int r = 0; r < 4; r++) acc[i][j][r] = 0.f;

    issue_chunk(sbase, Ab, Bb, 0, lr, lc);
    issue_chunk(sbase, Ab, Bb, 1, lr, lc);
    issue_chunk(sbase, Ab, Bb, 2, lr, lc);

    for (int c = 0; c < NCHUNK; c++) {
        asm volatile("cp.async.wait_group 2;" ::: "memory");
        __syncthreads();
        if (c + 3 < NCHUNK)
            issue_chunk(sbase, Ab, Bb, c + 3, lr, lc);
        else
            asm volatile("cp.async.commit_group;" ::: "memory");

        uint32_t sa = sbase + (c & (NSTG - 1)) * STG;
        uint32_t sb = sa + A_BYTES;

        #pragma unroll
        for (int ks = 0; ks < 4; ks++) {
            const uint32_t ch0 = ((2 * ks) ^ g) * 16 + t * 4;
            const uint32_t ch1 = ((2 * ks + 1) ^ g) * 16 + t * 4;
            uint32_t af[2][4], bf[8][2];
            #pragma unroll
            for (int i = 0; i < 2; i++) {
                uint32_t r0 = sa + (wm * 32 + i * 16 + g) * 128;
                uint32_t r8 = r0 + 8 * 128;
                af[i][0] = f2tf32(lds32(r0 + ch0));
                af[i][1] = f2tf32(lds32(r8 + ch0));
                af[i][2] = f2tf32(lds32(r0 + ch1));
                af[i][3] = f2tf32(lds32(r8 + ch1));
            }
            #pragma unroll
            for (int j = 0; j < 8; j++) {
                uint32_t rb = sb + (wn * 64 + j * 8 + g) * 128;
                bf[j][0] = f2tf32(lds32(rb + ch0));
                bf[j][1] = f2tf32(lds32(rb + ch1));
            }
            #pragma unroll
            for (int i = 0; i < 2; i++) {
                #pragma unroll
                for (int j = 0; j < 8; j++) {
                    asm volatile(
                        "mma.sync.aligned.m16n8k8.row.col.f32.tf32.tf32.f32 "
                        "{%0,%1,%2,%3}, {%4,%5,%6,%7}, {%8,%9}, {%0,%1,%2,%3};\n"
                        : "+f"(acc[i][j][0]), "+f"(acc[i][j][1]),
                          "+f"(acc[i][j][2]), "+f"(acc[i][j][3])
                        : "r"(af[i][0]), "r"(af[i][1]),
                          "r"(af[i][2]), "r"(af[i][3]),
                          "r"(bf[j][0]), "r"(bf[j][1]));
                }
            }
        }
    }

    // Epilogue: direct fp32 stores (DRAM ~8%; not a bottleneck).
    float* Cb = C + (size_t)b * NDIM * MDIM;
    #pragma unroll
    for (int i = 0; i < 2; i++) {
        int row = by * TM + wm * 32 + i * 16 + g;
        #pragma unroll
        for (int j = 0; j < 8; j++) {
            int col = bx * TN + wn * 64 + j * 8 + 2 * t;
            *(float2*)(Cb + (size_t)row * MDIM + col) =
                make_float2(acc[i][j][0], acc[i][j][1]);
            *(float2*)(Cb + (size_t)(row + 8) * MDIM + col) =
                make_float2(acc[i][j][2], acc[i][j][3]);
        }
    }
}

extern "C" void kernel_launch(void* const* d_in, const int* in_sizes, int n_in,
                              void* d_out, int out_size) {
    const float* mat0 = (const float*)d_in[0];   // [8, 2048, 1024]
    const float* mat1 = (const float*)d_in[1];   // [8, 2048, 1024]
    float* out = (float*)d_out;                  // [8, 2048, 2048]
    cudaFuncSetAttribute(bmm_tf32_v3,
                         cudaFuncAttributeMaxDynamicSharedMemorySize, SMEM_BYTES);
    dim3 grid(MDIM / TN, NDIM / TM, NB);         // (8, 16, 8)
    bmm_tf32_v3<<<grid, 512, SMEM_BYTES>>>(mat0, mat1, out);
}